// round 13
// baseline (speedup 1.0000x reference)
#include <cuda_runtime.h>
#include <cuda_fp16.h>
#include <math_constants.h>

#define BDIM 16
#define CDIM 64
#define HW   441
#define NCLS 10
#define MDIM 2205
#define NQT  4
#define NMT  18
#define NSTEP 144
#define NSPL 2
#define SPLS 72
#define EPSN 1e-12f

#define NA4 (BDIM * 4 * 4 * 2 * 4 * 32)
#define NB4 (NCLS * 2 * NMT * 8 * 2 * 32)

__device__ float g_qn[BDIM * HW * CDIM];
__device__ float g_rn[NCLS * MDIM];
__device__ uint4 g_af[NA4];
__device__ uint4 g_bf[NB4];
__device__ float4 g_rowtri[BDIM * NCLS * NQT * 128 * NSPL];

__device__ __forceinline__ unsigned int h2(float lo, float hi) {
    __half2 h = __floats2half2_rn(lo, hi);
    return *reinterpret_cast<unsigned int*>(&h);
}
__device__ __forceinline__ unsigned int maxh2(unsigned int a, unsigned int b) {
    unsigned int d; asm("max.f16x2 %0, %1, %2;" : "=r"(d) : "r"(a), "r"(b)); return d;
}
__device__ __forceinline__ unsigned int minh2(unsigned int a, unsigned int b) {
    unsigned int d; asm("min.f16x2 %0, %1, %2;" : "=r"(d) : "r"(a), "r"(b)); return d;
}
__device__ __forceinline__ void ins3p(unsigned int v, unsigned int &a0, unsigned int &a1, unsigned int &a2) {
    unsigned int n0 = minh2(a0, v); a0 = maxh2(a0, v);
    unsigned int n1 = minh2(a1, n0); a1 = maxh2(a1, n0);
    a2 = maxh2(a2, n1);
}
__device__ __forceinline__ void ins3f(float v, float &a0, float &a1, float &a2) {
    float n0 = fminf(a0, v); a0 = fmaxf(a0, v);
    float n1 = fminf(a1, n0); a1 = fmaxf(a1, n0);
    a2 = fmaxf(a2, n1);
}
// race-free packed merge: snapshot partner's triple BEFORE mutating own
__device__ __forceinline__ void merge3p_shfl(int sh, unsigned int &a0, unsigned int &a1, unsigned int &a2) {
    unsigned int o0 = __shfl_xor_sync(0xffffffffu, a0, sh);
    unsigned int o1 = __shfl_xor_sync(0xffffffffu, a1, sh);
    unsigned int o2 = __shfl_xor_sync(0xffffffffu, a2, sh);
    ins3p(o0, a0, a1, a2); ins3p(o1, a0, a1, a2); ins3p(o2, a0, a1, a2);
}
__device__ __forceinline__ void unp_ins(unsigned int p, float &a0, float &a1, float &a2) {
    float2 f = __half22float2(*reinterpret_cast<__half2*>(&p));
    ins3f(f.x, a0, a1, a2); ins3f(f.y, a0, a1, a2);
}
__device__ __forceinline__ void mma_f16(float c[4], uint4 a, unsigned int b0, unsigned int b1) {
    asm volatile("mma.sync.aligned.m16n8k16.row.col.f32.f16.f16.f32 "
                 "{%0,%1,%2,%3},{%4,%5,%6,%7},{%8,%9},{%0,%1,%2,%3};"
                 : "+f"(c[0]), "+f"(c[1]), "+f"(c[2]), "+f"(c[3])
                 : "r"(a.x), "r"(a.y), "r"(a.z), "r"(a.w), "r"(b0), "r"(b1));
}

// fused fp32 normalize (q and s in one launch)
__global__ void norm_kernel(const float* __restrict__ x1, const float* __restrict__ x2) {
    int idx = blockIdx.x * 256 + threadIdx.x;
    if (idx < BDIM * HW) {
        int b = idx / HW, p = idx - b * HW;
        const float* src = x1 + (b * CDIM) * HW + p;
        float v[CDIM]; float ss = 0.f;
#pragma unroll
        for (int c = 0; c < CDIM; c++) { float x = src[c * HW]; v[c] = x; ss += x * x; }
        float inv = 1.f / fmaxf(sqrtf(ss), EPSN);
        float* dst = g_qn + idx * CDIM;
#pragma unroll
        for (int c = 0; c < CDIM; c++) dst[c] = v[c] * inv;
    } else if (idx < BDIM * HW + NCLS * MDIM) {
        int j = idx - BDIM * HW;
        int n = j / MDIM, m = j - n * MDIM;
        const float* src = x2 + (n * CDIM) * MDIM + m;
        float ss = 0.f;
#pragma unroll
        for (int c = 0; c < CDIM; c++) { float x = src[c * MDIM]; ss += x * x; }
        g_rn[j] = 1.f / fmaxf(sqrtf(ss), EPSN);
    }
}

__global__ void frag_kernel(const float* __restrict__ x2) {
    int idx = blockIdx.x * 256 + threadIdx.x;
    if (idx < NA4) {
        int lane = idx & 31; int r = idx >> 5;
        int kc = r & 3;  r >>= 2;
        int blk = r & 1; r >>= 1;
        int rb = r & 3;  r >>= 2;
        int qt = r & 3;  int b = r >> 2;
        int q = qt * 128 + rb * 32 + blk * 16 + (lane >> 2);
        int k = kc * 16 + 2 * (lane & 3);
        float v0=0.f,v1=0.f,v2=0.f,v3=0.f,v4=0.f,v5=0.f,v6=0.f,v7=0.f;
        if (q < HW) {
            const float* p = g_qn + (b * HW + q) * CDIM;
            v0 = p[k]; v1 = p[k+1]; v2 = p[k+8]; v3 = p[k+9];
        }
        if (q + 8 < HW) {
            const float* p = g_qn + (b * HW + q + 8) * CDIM;
            v4 = p[k]; v5 = p[k+1]; v6 = p[k+8]; v7 = p[k+9];
        }
        uint4 o; o.x = h2(v0, v1); o.y = h2(v4, v5); o.z = h2(v2, v3); o.w = h2(v6, v7);
        g_af[idx] = o;
    } else if (idx < NA4 + NB4) {
        int j = idx - NA4;
        int lane = j & 31; int r = j >> 5;
        int kcp = r & 1; r >>= 1;
        int g = r & 7;   r >>= 3;
        int mt = r % 18; r /= 18;
        int half = r & 1; int n = r >> 1;
        int m = mt * 128 + half * 64 + g * 8 + (lane >> 2);
        int k0 = kcp * 32 + 2 * (lane & 3);
        uint4 o;
        if (m < MDIM) {
            float inv = g_rn[n * MDIM + m];
            const float* base = x2 + (n * CDIM) * MDIM + m;
            o.x = h2(base[(k0)      * MDIM] * inv, base[(k0 + 1)  * MDIM] * inv);
            o.y = h2(base[(k0 + 8)  * MDIM] * inv, base[(k0 + 9)  * MDIM] * inv);
            o.z = h2(base[(k0 + 16) * MDIM] * inv, base[(k0 + 17) * MDIM] * inv);
            o.w = h2(base[(k0 + 24) * MDIM] * inv, base[(k0 + 25) * MDIM] * inv);
        } else { o.x = o.y = o.z = o.w = 0u; }
        g_bf[j] = o;
    }
}

__global__ void noop_kernel() {}

__global__ void __launch_bounds__(256, 3)
fused_metric_kernel() {
    __shared__ unsigned int sRed[4 * 8 * 12];

    const int t = threadIdx.x;
    const int w = t >> 5, lane = t & 31, l3 = lane & 3;
    const int rb = w & 3, half = w >> 2;
    const int qt = blockIdx.x >> 1, ms = blockIdx.x & 1;
    const int n = blockIdx.y, b = blockIdx.z;
    const int s0 = ms * SPLS, s1 = s0 + SPLS;

    uint4 aR[2][4];
    {
        const uint4* pa = g_af + ((((b * 4 + qt) * 4 + rb) * 2) * 4) * 32 + lane;
#pragma unroll
        for (int blk = 0; blk < 2; blk++)
#pragma unroll
            for (int kc = 0; kc < 4; kc++) aR[blk][kc] = pa[(blk * 4 + kc) * 32];
    }

    const uint4* baseB = g_bf + (n * 2 + half) * 9216 + lane;

    unsigned int A0a = 0xFC00FC00u, A0b = 0xFC00FC00u, A0c = 0xFC00FC00u;
    unsigned int B0a = 0xFC00FC00u, B0b = 0xFC00FC00u, B0c = 0xFC00FC00u;
    unsigned int A1a = 0xFC00FC00u, A1b = 0xFC00FC00u, A1c = 0xFC00FC00u;
    unsigned int B1a = 0xFC00FC00u, B1b = 0xFC00FC00u, B1c = 0xFC00FC00u;

    uint4 c0 = baseB[s0 * 64], c1 = baseB[s0 * 64 + 32];
    const int sMask = (s1 < NSTEP - 8) ? s1 : NSTEP - 8;

#pragma unroll 1
    for (int s = s0; s < s1; s++) {
        int ns = s + 1 < s1 ? s + 1 : s;
        const uint4* pn = baseB + ns * 64;
        // L1 prefetch 2 steps ahead (hides L2-hit latency on the B stream)
        {
            int pf = s + 2 < s1 ? s + 2 : s;
            const char* pp = (const char*)(baseB + pf * 64);
            asm volatile("prefetch.global.L1 [%0];" :: "l"(pp));
            asm volatile("prefetch.global.L1 [%0];" :: "l"(pp + 512));
        }
        uint4 n0 = pn[0], n1 = pn[32];

        float acc0[4] = {0.f, 0.f, 0.f, 0.f};
        float acc1[4] = {0.f, 0.f, 0.f, 0.f};
        mma_f16(acc0, aR[0][0], c0.x, c0.y);
        mma_f16(acc0, aR[0][1], c0.z, c0.w);
        mma_f16(acc0, aR[0][2], c1.x, c1.y);
        mma_f16(acc0, aR[0][3], c1.z, c1.w);
        mma_f16(acc1, aR[1][0], c0.x, c0.y);
        mma_f16(acc1, aR[1][1], c0.z, c0.w);
        mma_f16(acc1, aR[1][2], c1.x, c1.y);
        mma_f16(acc1, aR[1][3], c1.z, c1.w);
        c0 = n0; c1 = n1;

        if (s < sMask) {
            ins3p(h2(acc0[0], acc0[1]), A0a, A0b, A0c);
            ins3p(h2(acc0[2], acc0[3]), B0a, B0b, B0c);
            ins3p(h2(acc1[0], acc1[1]), A1a, A1b, A1c);
            ins3p(h2(acc1[2], acc1[3]), B1a, B1b, B1c);
        } else if (half == 0) {      // last m-tile: valid cols 0..28 (2205 = 17*128 + 29)
            const float NI = -CUDART_INF_F;
            int col = (s & 7) * 8 + 2 * l3;
            float e0 = (col < 29) ? acc0[0] : NI, e1 = (col + 1 < 29) ? acc0[1] : NI;
            float e2 = (col < 29) ? acc0[2] : NI, e3 = (col + 1 < 29) ? acc0[3] : NI;
            float e4 = (col < 29) ? acc1[0] : NI, e5 = (col + 1 < 29) ? acc1[1] : NI;
            float e6 = (col < 29) ? acc1[2] : NI, e7 = (col + 1 < 29) ? acc1[3] : NI;
            ins3p(h2(e0, e1), A0a, A0b, A0c);
            ins3p(h2(e2, e3), B0a, B0b, B0c);
            ins3p(h2(e4, e5), A1a, A1b, A1c);
            ins3p(h2(e6, e7), B1a, B1b, B1c);
        }
    }

#pragma unroll
    for (int sh = 1; sh <= 2; sh <<= 1) {
        merge3p_shfl(sh, A0a, A0b, A0c);
        merge3p_shfl(sh, B0a, B0b, B0c);
        merge3p_shfl(sh, A1a, A1b, A1c);
        merge3p_shfl(sh, B1a, B1b, B1c);
    }

    if (w >= 4 && l3 == 0) {
        unsigned int* d = sRed + (rb * 8 + (lane >> 2)) * 12;
        d[0] = A0a; d[1] = A0b; d[2]  = A0c; d[3]  = B0a; d[4]  = B0b; d[5]  = B0c;
        d[6] = A1a; d[7] = A1b; d[8]  = A1c; d[9]  = B1a; d[10] = B1b; d[11] = B1c;
    }
    __syncthreads();
    if (w < 4 && l3 == 0) {
        const unsigned int* d = sRed + (rb * 8 + (lane >> 2)) * 12;
        ins3p(d[0], A0a, A0b, A0c); ins3p(d[1], A0a, A0b, A0c); ins3p(d[2], A0a, A0b, A0c);
        ins3p(d[3], B0a, B0b, B0c); ins3p(d[4], B0a, B0b, B0c); ins3p(d[5], B0a, B0b, B0c);
        ins3p(d[6], A1a, A1b, A1c); ins3p(d[7], A1a, A1b, A1c); ins3p(d[8], A1a, A1b, A1c);
        ins3p(d[9], B1a, B1b, B1c); ins3p(d[10], B1a, B1b, B1c); ins3p(d[11], B1a, B1b, B1c);

        const int entry = (b * NCLS + n) * NQT + qt;
        const int row0 = rb * 32 + (lane >> 2);
        float4* outp = g_rowtri + ((long)entry * 128) * NSPL + ms;
        {
            float u0 = -CUDART_INF_F, u1 = u0, u2 = u0;
            unp_ins(A0a, u0, u1, u2); unp_ins(A0b, u0, u1, u2); unp_ins(A0c, u0, u1, u2);
            outp[(row0) * NSPL] = make_float4(u0, u1, u2, 0.f);
        }
        {
            float u0 = -CUDART_INF_F, u1 = u0, u2 = u0;
            unp_ins(B0a, u0, u1, u2); unp_ins(B0b, u0, u1, u2); unp_ins(B0c, u0, u1, u2);
            outp[(row0 + 8) * NSPL] = make_float4(u0, u1, u2, 0.f);
        }
        {
            float u0 = -CUDART_INF_F, u1 = u0, u2 = u0;
            unp_ins(A1a, u0, u1, u2); unp_ins(A1b, u0, u1, u2); unp_ins(A1c, u0, u1, u2);
            outp[(row0 + 16) * NSPL] = make_float4(u0, u1, u2, 0.f);
        }
        {
            float u0 = -CUDART_INF_F, u1 = u0, u2 = u0;
            unp_ins(B1a, u0, u1, u2); unp_ins(B1b, u0, u1, u2); unp_ins(B1c, u0, u1, u2);
            outp[(row0 + 24) * NSPL] = make_float4(u0, u1, u2, 0.f);
        }
    }
}

// merge the NSPL split-triples per row, sum top-3, reduce over rows
__global__ void finalize_kernel(float* __restrict__ out) {
    __shared__ float red[16];
    const int e = blockIdx.x;          // b*NCLS + n
    const int q = threadIdx.x;         // 0..511
    float val = 0.f;
    if (q < HW) {
        int qt = q >> 7, row = q & 127;
        const float4* p = g_rowtri + ((long)((e * NQT + qt) * 128 + row)) * NSPL;
        float4 u = p[0], v = p[1];
        float t0 = u.x, t1 = u.y, t2 = u.z;
        ins3f(v.x, t0, t1, t2); ins3f(v.y, t0, t1, t2); ins3f(v.z, t0, t1, t2);
        val = t0 + t1 + t2;
    }
    const int w = q >> 5, lane = q & 31;
#pragma unroll
    for (int sh = 16; sh > 0; sh >>= 1) val += __shfl_xor_sync(0xffffffffu, val, sh);
    if (lane == 0) red[w] = val;
    __syncthreads();
    if (w == 0) {
        float x = (lane < 16) ? red[lane] : 0.f;
#pragma unroll
        for (int sh = 8; sh > 0; sh >>= 1) x += __shfl_xor_sync(0xffffffffu, x, sh);
        if (lane == 0) out[e] = x;
    }
}

extern "C" void kernel_launch(void* const* d_in, const int* in_sizes, int n_in,
                              void* d_out, int out_size) {
    const float* x1 = (const float*)d_in[0];
    const float* x2 = (const float*)d_in[1];
    float* out = (float*)d_out;

    noop_kernel<<<1, 32>>>();   // keeps fused kernel at overall launch idx 5 for ncu
    norm_kernel<<<(BDIM * HW + NCLS * MDIM + 255) / 256, 256>>>(x1, x2);
    frag_kernel<<<(NA4 + NB4 + 255) / 256, 256>>>(x2);
    fused_metric_kernel<<<dim3(NQT * NSPL, NCLS, BDIM), 256>>>();
    finalize_kernel<<<BDIM * NCLS, 512>>>(out);
}

// round 14
// speedup vs baseline: 1.1315x; 1.1315x over previous
#include <cuda_runtime.h>
#include <cuda_fp16.h>
#include <math_constants.h>

#define BDIM 16
#define CDIM 64
#define HW   441
#define NCLS 10
#define MDIM 2205
#define NQT  4
#define NMT  18
#define NSTEP 144
#define NSPL 2
#define SPLS 72
#define EPSN 1e-12f

#define NA4 (BDIM * 4 * 4 * 2 * 4 * 32)
#define NB4 (NCLS * 2 * NMT * 8 * 2 * 32)

__device__ float g_qn[BDIM * HW * CDIM];
__device__ float g_rn[NCLS * MDIM];
__device__ uint4 g_af[NA4];
__device__ uint4 g_bf[NB4];
__device__ float4 g_rowtri[BDIM * NCLS * NQT * 128 * NSPL];
__device__ int   g_cnt[BDIM * NCLS];    // zero-init; self-resetting per replay

__device__ __forceinline__ unsigned int h2(float lo, float hi) {
    __half2 h = __floats2half2_rn(lo, hi);
    return *reinterpret_cast<unsigned int*>(&h);
}
__device__ __forceinline__ unsigned int maxh2(unsigned int a, unsigned int b) {
    unsigned int d; asm("max.f16x2 %0, %1, %2;" : "=r"(d) : "r"(a), "r"(b)); return d;
}
__device__ __forceinline__ unsigned int minh2(unsigned int a, unsigned int b) {
    unsigned int d; asm("min.f16x2 %0, %1, %2;" : "=r"(d) : "r"(a), "r"(b)); return d;
}
__device__ __forceinline__ void ins3p(unsigned int v, unsigned int &a0, unsigned int &a1, unsigned int &a2) {
    unsigned int n0 = minh2(a0, v); a0 = maxh2(a0, v);
    unsigned int n1 = minh2(a1, n0); a1 = maxh2(a1, n0);
    a2 = maxh2(a2, n1);
}
__device__ __forceinline__ void ins3f(float v, float &a0, float &a1, float &a2) {
    float n0 = fminf(a0, v); a0 = fmaxf(a0, v);
    float n1 = fminf(a1, n0); a1 = fmaxf(a1, n0);
    a2 = fmaxf(a2, n1);
}
// race-free packed merge: snapshot partner's triple BEFORE mutating own
__device__ __forceinline__ void merge3p_shfl(int sh, unsigned int &a0, unsigned int &a1, unsigned int &a2) {
    unsigned int o0 = __shfl_xor_sync(0xffffffffu, a0, sh);
    unsigned int o1 = __shfl_xor_sync(0xffffffffu, a1, sh);
    unsigned int o2 = __shfl_xor_sync(0xffffffffu, a2, sh);
    ins3p(o0, a0, a1, a2); ins3p(o1, a0, a1, a2); ins3p(o2, a0, a1, a2);
}
__device__ __forceinline__ void unp_ins(unsigned int p, float &a0, float &a1, float &a2) {
    float2 f = __half22float2(*reinterpret_cast<__half2*>(&p));
    ins3f(f.x, a0, a1, a2); ins3f(f.y, a0, a1, a2);
}
__device__ __forceinline__ void mma_f16(float c[4], uint4 a, unsigned int b0, unsigned int b1) {
    asm volatile("mma.sync.aligned.m16n8k16.row.col.f32.f16.f16.f32 "
                 "{%0,%1,%2,%3},{%4,%5,%6,%7},{%8,%9},{%0,%1,%2,%3};"
                 : "+f"(c[0]), "+f"(c[1]), "+f"(c[2]), "+f"(c[3])
                 : "r"(a.x), "r"(a.y), "r"(a.z), "r"(a.w), "r"(b0), "r"(b1));
}

// fused fp32 normalize (q and s in one launch)
__global__ void norm_kernel(const float* __restrict__ x1, const float* __restrict__ x2) {
    int idx = blockIdx.x * 256 + threadIdx.x;
    if (idx < BDIM * HW) {
        int b = idx / HW, p = idx - b * HW;
        const float* src = x1 + (b * CDIM) * HW + p;
        float v[CDIM]; float ss = 0.f;
#pragma unroll
        for (int c = 0; c < CDIM; c++) { float x = src[c * HW]; v[c] = x; ss += x * x; }
        float inv = 1.f / fmaxf(sqrtf(ss), EPSN);
        float* dst = g_qn + idx * CDIM;
#pragma unroll
        for (int c = 0; c < CDIM; c++) dst[c] = v[c] * inv;
    } else if (idx < BDIM * HW + NCLS * MDIM) {
        int j = idx - BDIM * HW;
        int n = j / MDIM, m = j - n * MDIM;
        const float* src = x2 + (n * CDIM) * MDIM + m;
        float ss = 0.f;
#pragma unroll
        for (int c = 0; c < CDIM; c++) { float x = src[c * MDIM]; ss += x * x; }
        g_rn[j] = 1.f / fmaxf(sqrtf(ss), EPSN);
    }
}

__global__ void frag_kernel(const float* __restrict__ x2) {
    int idx = blockIdx.x * 256 + threadIdx.x;
    if (idx < NA4) {
        int lane = idx & 31; int r = idx >> 5;
        int kc = r & 3;  r >>= 2;
        int blk = r & 1; r >>= 1;
        int rb = r & 3;  r >>= 2;
        int qt = r & 3;  int b = r >> 2;
        int q = qt * 128 + rb * 32 + blk * 16 + (lane >> 2);
        int k = kc * 16 + 2 * (lane & 3);
        float v0=0.f,v1=0.f,v2=0.f,v3=0.f,v4=0.f,v5=0.f,v6=0.f,v7=0.f;
        if (q < HW) {
            const float* p = g_qn + (b * HW + q) * CDIM;
            v0 = p[k]; v1 = p[k+1]; v2 = p[k+8]; v3 = p[k+9];
        }
        if (q + 8 < HW) {
            const float* p = g_qn + (b * HW + q + 8) * CDIM;
            v4 = p[k]; v5 = p[k+1]; v6 = p[k+8]; v7 = p[k+9];
        }
        uint4 o; o.x = h2(v0, v1); o.y = h2(v4, v5); o.z = h2(v2, v3); o.w = h2(v6, v7);
        g_af[idx] = o;
    } else if (idx < NA4 + NB4) {
        int j = idx - NA4;
        int lane = j & 31; int r = j >> 5;
        int kcp = r & 1; r >>= 1;
        int g = r & 7;   r >>= 3;
        int mt = r % 18; r /= 18;
        int half = r & 1; int n = r >> 1;
        int m = mt * 128 + half * 64 + g * 8 + (lane >> 2);
        int k0 = kcp * 32 + 2 * (lane & 3);
        uint4 o;
        if (m < MDIM) {
            float inv = g_rn[n * MDIM + m];
            const float* base = x2 + (n * CDIM) * MDIM + m;
            o.x = h2(base[(k0)      * MDIM] * inv, base[(k0 + 1)  * MDIM] * inv);
            o.y = h2(base[(k0 + 8)  * MDIM] * inv, base[(k0 + 9)  * MDIM] * inv);
            o.z = h2(base[(k0 + 16) * MDIM] * inv, base[(k0 + 17) * MDIM] * inv);
            o.w = h2(base[(k0 + 24) * MDIM] * inv, base[(k0 + 25) * MDIM] * inv);
        } else { o.x = o.y = o.z = o.w = 0u; }
        g_bf[j] = o;
    }
}

__global__ void __launch_bounds__(256, 3)
fused_metric_kernel(float* __restrict__ out) {
    __shared__ unsigned int sRed[4 * 8 * 12];
    __shared__ float sVal[8];
    __shared__ int sLast;

    const int t = threadIdx.x;
    const int w = t >> 5, lane = t & 31, l3 = lane & 3;
    const int rb = w & 3, half = w >> 2;
    const int qt = blockIdx.x >> 1, ms = blockIdx.x & 1;
    const int n = blockIdx.y, b = blockIdx.z;
    const int s0 = ms * SPLS, s1 = s0 + SPLS;
    const int eBN = b * NCLS + n;

    uint4 aR[2][4];
    {
        const uint4* pa = g_af + ((((b * 4 + qt) * 4 + rb) * 2) * 4) * 32 + lane;
#pragma unroll
        for (int blk = 0; blk < 2; blk++)
#pragma unroll
            for (int kc = 0; kc < 4; kc++) aR[blk][kc] = pa[(blk * 4 + kc) * 32];
    }

    const uint4* baseB = g_bf + (n * 2 + half) * 9216 + lane;

    unsigned int A0a = 0xFC00FC00u, A0b = 0xFC00FC00u, A0c = 0xFC00FC00u;
    unsigned int B0a = 0xFC00FC00u, B0b = 0xFC00FC00u, B0c = 0xFC00FC00u;
    unsigned int A1a = 0xFC00FC00u, A1b = 0xFC00FC00u, A1c = 0xFC00FC00u;
    unsigned int B1a = 0xFC00FC00u, B1b = 0xFC00FC00u, B1c = 0xFC00FC00u;

    const int sMask = (s1 < NSTEP - 8) ? s1 : NSTEP - 8;

    // one body step: consume d0,d1 at step s
    auto body = [&](const uint4 &d0, const uint4 &d1, int s) {
        float acc0[4] = {0.f, 0.f, 0.f, 0.f};
        float acc1[4] = {0.f, 0.f, 0.f, 0.f};
        mma_f16(acc0, aR[0][0], d0.x, d0.y);
        mma_f16(acc0, aR[0][1], d0.z, d0.w);
        mma_f16(acc0, aR[0][2], d1.x, d1.y);
        mma_f16(acc0, aR[0][3], d1.z, d1.w);
        mma_f16(acc1, aR[1][0], d0.x, d0.y);
        mma_f16(acc1, aR[1][1], d0.z, d0.w);
        mma_f16(acc1, aR[1][2], d1.x, d1.y);
        mma_f16(acc1, aR[1][3], d1.z, d1.w);
        if (s < sMask) {
            ins3p(h2(acc0[0], acc0[1]), A0a, A0b, A0c);
            ins3p(h2(acc0[2], acc0[3]), B0a, B0b, B0c);
            ins3p(h2(acc1[0], acc1[1]), A1a, A1b, A1c);
            ins3p(h2(acc1[2], acc1[3]), B1a, B1b, B1c);
        } else if (half == 0) {     // last m-tile: valid cols 0..28 (2205 = 17*128 + 29)
            const float NI = -CUDART_INF_F;
            int col = (s & 7) * 8 + 2 * l3;
            float e0 = (col < 29) ? acc0[0] : NI, e1 = (col + 1 < 29) ? acc0[1] : NI;
            float e2 = (col < 29) ? acc0[2] : NI, e3 = (col + 1 < 29) ? acc0[3] : NI;
            float e4 = (col < 29) ? acc1[0] : NI, e5 = (col + 1 < 29) ? acc1[1] : NI;
            float e6 = (col < 29) ? acc1[2] : NI, e7 = (col + 1 < 29) ? acc1[3] : NI;
            ins3p(h2(e0, e1), A0a, A0b, A0c);
            ins3p(h2(e2, e3), B0a, B0b, B0c);
            ins3p(h2(e4, e5), A1a, A1b, A1c);
            ins3p(h2(e6, e7), B1a, B1b, B1c);
        }
    };

    // unroll-2 ping-pong mainloop: no register copies (SPLS even)
    uint4 c0 = baseB[s0 * 64], c1 = baseB[s0 * 64 + 32];
#pragma unroll 1
    for (int s = s0; s < s1; s += 2) {
        const uint4* p1 = baseB + (s + 1) * 64;
        uint4 n0 = p1[0], n1 = p1[32];
        body(c0, c1, s);
        int s2 = (s + 2 < s1) ? s + 2 : s1 - 1;   // clamp (avoid OOB on last pair)
        const uint4* p2 = baseB + s2 * 64;
        c0 = p2[0]; c1 = p2[32];
        body(n0, n1, s + 1);
    }

#pragma unroll
    for (int sh = 1; sh <= 2; sh <<= 1) {
        merge3p_shfl(sh, A0a, A0b, A0c);
        merge3p_shfl(sh, B0a, B0b, B0c);
        merge3p_shfl(sh, A1a, A1b, A1c);
        merge3p_shfl(sh, B1a, B1b, B1c);
    }

    if (w >= 4 && l3 == 0) {
        unsigned int* d = sRed + (rb * 8 + (lane >> 2)) * 12;
        d[0] = A0a; d[1] = A0b; d[2]  = A0c; d[3]  = B0a; d[4]  = B0b; d[5]  = B0c;
        d[6] = A1a; d[7] = A1b; d[8]  = A1c; d[9]  = B1a; d[10] = B1b; d[11] = B1c;
    }
    __syncthreads();
    if (w < 4 && l3 == 0) {
        const unsigned int* d = sRed + (rb * 8 + (lane >> 2)) * 12;
        ins3p(d[0], A0a, A0b, A0c); ins3p(d[1], A0a, A0b, A0c); ins3p(d[2], A0a, A0b, A0c);
        ins3p(d[3], B0a, B0b, B0c); ins3p(d[4], B0a, B0b, B0c); ins3p(d[5], B0a, B0b, B0c);
        ins3p(d[6], A1a, A1b, A1c); ins3p(d[7], A1a, A1b, A1c); ins3p(d[8], A1a, A1b, A1c);
        ins3p(d[9], B1a, B1b, B1c); ins3p(d[10], B1a, B1b, B1c); ins3p(d[11], B1a, B1b, B1c);

        const int entry = eBN * NQT + qt;
        const int row0 = rb * 32 + (lane >> 2);
        float4* outp = g_rowtri + ((long)entry * 128) * NSPL + ms;
        {
            float u0 = -CUDART_INF_F, u1 = u0, u2 = u0;
            unp_ins(A0a, u0, u1, u2); unp_ins(A0b, u0, u1, u2); unp_ins(A0c, u0, u1, u2);
            outp[(row0) * NSPL] = make_float4(u0, u1, u2, 0.f);
        }
        {
            float u0 = -CUDART_INF_F, u1 = u0, u2 = u0;
            unp_ins(B0a, u0, u1, u2); unp_ins(B0b, u0, u1, u2); unp_ins(B0c, u0, u1, u2);
            outp[(row0 + 8) * NSPL] = make_float4(u0, u1, u2, 0.f);
        }
        {
            float u0 = -CUDART_INF_F, u1 = u0, u2 = u0;
            unp_ins(A1a, u0, u1, u2); unp_ins(A1b, u0, u1, u2); unp_ins(A1c, u0, u1, u2);
            outp[(row0 + 16) * NSPL] = make_float4(u0, u1, u2, 0.f);
        }
        {
            float u0 = -CUDART_INF_F, u1 = u0, u2 = u0;
            unp_ins(B1a, u0, u1, u2); unp_ins(B1b, u0, u1, u2); unp_ins(B1c, u0, u1, u2);
            outp[(row0 + 24) * NSPL] = make_float4(u0, u1, u2, 0.f);
        }
    }

    // ---- fused finalize: last of the 8 CTAs for this (b,n) reduces & writes out ----
    __threadfence();
    __syncthreads();
    if (t == 0) {
        int old = atomicAdd(&g_cnt[eBN], 1);
        sLast = (old == 7) ? 1 : 0;
    }
    __syncthreads();
    if (!sLast) return;
    if (t == 0) g_cnt[eBN] = 0;     // self-reset for graph replay

    float val = 0.f;
#pragma unroll
    for (int i = 0; i < 2; i++) {
        int r = t + i * 256;        // 512 row slots; padded rows hold {0,0,0} -> contribute 0
        int qti = r >> 7, row = r & 127;
        const float4* p = g_rowtri + ((long)((eBN * NQT + qti) * 128 + row)) * NSPL;
        float4 u = p[0], v = p[1];
        float t0 = u.x, t1 = u.y, t2 = u.z;
        ins3f(v.x, t0, t1, t2); ins3f(v.y, t0, t1, t2); ins3f(v.z, t0, t1, t2);
        val += t0 + t1 + t2;
    }
#pragma unroll
    for (int sh = 16; sh > 0; sh >>= 1) val += __shfl_xor_sync(0xffffffffu, val, sh);
    if (lane == 0) sVal[w] = val;
    __syncthreads();
    if (t == 0) {
        float x = 0.f;
#pragma unroll
        for (int i = 0; i < 8; i++) x += sVal[i];
        out[eBN] = x;
    }
}

extern "C" void kernel_launch(void* const* d_in, const int* in_sizes, int n_in,
                              void* d_out, int out_size) {
    const float* x1 = (const float*)d_in[0];
    const float* x2 = (const float*)d_in[1];
    float* out = (float*)d_out;

    norm_kernel<<<(BDIM * HW + NCLS * MDIM + 255) / 256, 256>>>(x1, x2);
    frag_kernel<<<(NA4 + NB4 + 255) / 256, 256>>>(x2);
    fused_metric_kernel<<<dim3(NQT * NSPL, NCLS, BDIM), 256>>>(out);
}

// round 15
// speedup vs baseline: 1.2156x; 1.0743x over previous
#include <cuda_runtime.h>
#include <cuda_fp16.h>
#include <math_constants.h>

#define BDIM 16
#define CDIM 64
#define HW   441
#define NCLS 10
#define MDIM 2205
#define NQT  4
#define NMT  18
#define NSTEP 144
#define NSPL 2
#define SPLS 72
#define EPSN 1e-12f

#define NA4 (BDIM * 4 * 4 * 2 * 4 * 32)
#define NB4 (NCLS * 2 * NMT * 8 * 2 * 32)
#define NROWQ (BDIM * HW)            // 7056
#define NROWS (NCLS * MDIM)          // 22050
#define NROW  (NROWQ + NROWS)        // 29106

__device__ float g_qn[BDIM * HW * CDIM];
__device__ float g_rn[NCLS * MDIM];
__device__ uint4 g_af[NA4];
__device__ uint4 g_bf[NB4];
__device__ float4 g_rowtri[BDIM * NCLS * NQT * 128 * NSPL];
__device__ int   g_cnt[BDIM * NCLS];    // zero-init; self-resetting per replay

__device__ __forceinline__ unsigned int h2(float lo, float hi) {
    __half2 h = __floats2half2_rn(lo, hi);
    return *reinterpret_cast<unsigned int*>(&h);
}
__device__ __forceinline__ unsigned int maxh2(unsigned int a, unsigned int b) {
    unsigned int d; asm("max.f16x2 %0, %1, %2;" : "=r"(d) : "r"(a), "r"(b)); return d;
}
__device__ __forceinline__ unsigned int minh2(unsigned int a, unsigned int b) {
    unsigned int d; asm("min.f16x2 %0, %1, %2;" : "=r"(d) : "r"(a), "r"(b)); return d;
}
__device__ __forceinline__ void ins3p(unsigned int v, unsigned int &a0, unsigned int &a1, unsigned int &a2) {
    unsigned int n0 = minh2(a0, v); a0 = maxh2(a0, v);
    unsigned int n1 = minh2(a1, n0); a1 = maxh2(a1, n0);
    a2 = maxh2(a2, n1);
}
__device__ __forceinline__ void ins3f(float v, float &a0, float &a1, float &a2) {
    float n0 = fminf(a0, v); a0 = fmaxf(a0, v);
    float n1 = fminf(a1, n0); a1 = fmaxf(a1, n0);
    a2 = fmaxf(a2, n1);
}
// race-free packed merge: snapshot partner's triple BEFORE mutating own
__device__ __forceinline__ void merge3p_shfl(int sh, unsigned int &a0, unsigned int &a1, unsigned int &a2) {
    unsigned int o0 = __shfl_xor_sync(0xffffffffu, a0, sh);
    unsigned int o1 = __shfl_xor_sync(0xffffffffu, a1, sh);
    unsigned int o2 = __shfl_xor_sync(0xffffffffu, a2, sh);
    ins3p(o0, a0, a1, a2); ins3p(o1, a0, a1, a2); ins3p(o2, a0, a1, a2);
}
__device__ __forceinline__ void unp_ins(unsigned int p, float &a0, float &a1, float &a2) {
    float2 f = __half22float2(*reinterpret_cast<__half2*>(&p));
    ins3f(f.x, a0, a1, a2); ins3f(f.y, a0, a1, a2);
}
__device__ __forceinline__ void mma_f16(float c[4], uint4 a, unsigned int b0, unsigned int b1) {
    asm volatile("mma.sync.aligned.m16n8k16.row.col.f32.f16.f16.f32 "
                 "{%0,%1,%2,%3},{%4,%5,%6,%7},{%8,%9},{%0,%1,%2,%3};"
                 : "+f"(c[0]), "+f"(c[1]), "+f"(c[2]), "+f"(c[3])
                 : "r"(a.x), "r"(a.y), "r"(a.z), "r"(a.w), "r"(b0), "r"(b1));
}

// warp-per-row normalize: lane loads c=lane and c=lane+32, shfl-reduce, coalesced write
__global__ void norm_kernel(const float* __restrict__ x1, const float* __restrict__ x2) {
    int r = (blockIdx.x * 256 + threadIdx.x) >> 5;
    int lane = threadIdx.x & 31;
    if (r < NROWQ) {
        int b = r / HW, p = r - b * HW;
        const float* src = x1 + (b * CDIM) * HW + p;
        float x = src[lane * HW];
        float y = src[(lane + 32) * HW];
        float ss = x * x + y * y;
#pragma unroll
        for (int sh = 16; sh > 0; sh >>= 1) ss += __shfl_xor_sync(0xffffffffu, ss, sh);
        float inv = 1.f / fmaxf(sqrtf(ss), EPSN);
        float* dst = g_qn + r * CDIM;
        dst[lane] = x * inv;
        dst[lane + 32] = y * inv;
    } else if (r < NROW) {
        int j = r - NROWQ;
        int n = j / MDIM, m = j - n * MDIM;
        const float* src = x2 + (n * CDIM) * MDIM + m;
        float x = src[lane * MDIM];
        float y = src[(lane + 32) * MDIM];
        float ss = x * x + y * y;
#pragma unroll
        for (int sh = 16; sh > 0; sh >>= 1) ss += __shfl_xor_sync(0xffffffffu, ss, sh);
        if (lane == 0) g_rn[j] = 1.f / fmaxf(sqrtf(ss), EPSN);
    }
}

__global__ void frag_kernel(const float* __restrict__ x2) {
    int idx = blockIdx.x * 256 + threadIdx.x;
    if (idx < NA4) {
        int lane = idx & 31; int r = idx >> 5;
        int kc = r & 3;  r >>= 2;
        int blk = r & 1; r >>= 1;
        int rb = r & 3;  r >>= 2;
        int qt = r & 3;  int b = r >> 2;
        int q = qt * 128 + rb * 32 + blk * 16 + (lane >> 2);
        int k = kc * 16 + 2 * (lane & 3);
        float v0=0.f,v1=0.f,v2=0.f,v3=0.f,v4=0.f,v5=0.f,v6=0.f,v7=0.f;
        if (q < HW) {
            const float* p = g_qn + (b * HW + q) * CDIM;
            v0 = p[k]; v1 = p[k+1]; v2 = p[k+8]; v3 = p[k+9];
        }
        if (q + 8 < HW) {
            const float* p = g_qn + (b * HW + q + 8) * CDIM;
            v4 = p[k]; v5 = p[k+1]; v6 = p[k+8]; v7 = p[k+9];
        }
        uint4 o; o.x = h2(v0, v1); o.y = h2(v4, v5); o.z = h2(v2, v3); o.w = h2(v6, v7);
        g_af[idx] = o;
    } else if (idx < NA4 + NB4) {
        int j = idx - NA4;
        int lane = j & 31; int r = j >> 5;
        int kcp = r & 1; r >>= 1;
        int g = r & 7;   r >>= 3;
        int mt = r % 18; r /= 18;
        int half = r & 1; int n = r >> 1;
        int m = mt * 128 + half * 64 + g * 8 + (lane >> 2);
        int k0 = kcp * 32 + 2 * (lane & 3);
        uint4 o;
        if (m < MDIM) {
            float inv = g_rn[n * MDIM + m];
            const float* base = x2 + (n * CDIM) * MDIM + m;
            o.x = h2(base[(k0)      * MDIM] * inv, base[(k0 + 1)  * MDIM] * inv);
            o.y = h2(base[(k0 + 8)  * MDIM] * inv, base[(k0 + 9)  * MDIM] * inv);
            o.z = h2(base[(k0 + 16) * MDIM] * inv, base[(k0 + 17) * MDIM] * inv);
            o.w = h2(base[(k0 + 24) * MDIM] * inv, base[(k0 + 25) * MDIM] * inv);
        } else { o.x = o.y = o.z = o.w = 0u; }
        g_bf[j] = o;
    }
}

__global__ void noop_kernel() {}

__global__ void __launch_bounds__(256, 3)
fused_metric_kernel(float* __restrict__ out) {
    __shared__ unsigned int sRed[4 * 8 * 12];
    __shared__ float sVal[8];
    __shared__ int sLast;

    const int t = threadIdx.x;
    const int w = t >> 5, lane = t & 31, l3 = lane & 3;
    const int rb = w & 3, half = w >> 2;
    const int qt = blockIdx.x >> 1, ms = blockIdx.x & 1;
    const int n = blockIdx.y, b = blockIdx.z;
    const int s0 = ms * SPLS, s1 = s0 + SPLS;
    const int eBN = b * NCLS + n;

    uint4 aR[2][4];
    {
        const uint4* pa = g_af + ((((b * 4 + qt) * 4 + rb) * 2) * 4) * 32 + lane;
#pragma unroll
        for (int blk = 0; blk < 2; blk++)
#pragma unroll
            for (int kc = 0; kc < 4; kc++) aR[blk][kc] = pa[(blk * 4 + kc) * 32];
    }

    const uint4* baseB = g_bf + (n * 2 + half) * 9216 + lane;

    unsigned int A0a = 0xFC00FC00u, A0b = 0xFC00FC00u, A0c = 0xFC00FC00u;
    unsigned int B0a = 0xFC00FC00u, B0b = 0xFC00FC00u, B0c = 0xFC00FC00u;
    unsigned int A1a = 0xFC00FC00u, A1b = 0xFC00FC00u, A1c = 0xFC00FC00u;
    unsigned int B1a = 0xFC00FC00u, B1b = 0xFC00FC00u, B1c = 0xFC00FC00u;

    const int sMask = (s1 < NSTEP - 8) ? s1 : NSTEP - 8;

    auto body = [&](const uint4 &d0, const uint4 &d1, int s) {
        float acc0[4] = {0.f, 0.f, 0.f, 0.f};
        float acc1[4] = {0.f, 0.f, 0.f, 0.f};
        mma_f16(acc0, aR[0][0], d0.x, d0.y);
        mma_f16(acc0, aR[0][1], d0.z, d0.w);
        mma_f16(acc0, aR[0][2], d1.x, d1.y);
        mma_f16(acc0, aR[0][3], d1.z, d1.w);
        mma_f16(acc1, aR[1][0], d0.x, d0.y);
        mma_f16(acc1, aR[1][1], d0.z, d0.w);
        mma_f16(acc1, aR[1][2], d1.x, d1.y);
        mma_f16(acc1, aR[1][3], d1.z, d1.w);
        if (s < sMask) {
            ins3p(h2(acc0[0], acc0[1]), A0a, A0b, A0c);
            ins3p(h2(acc0[2], acc0[3]), B0a, B0b, B0c);
            ins3p(h2(acc1[0], acc1[1]), A1a, A1b, A1c);
            ins3p(h2(acc1[2], acc1[3]), B1a, B1b, B1c);
        } else if (half == 0) {     // last m-tile: valid cols 0..28 (2205 = 17*128 + 29)
            const float NI = -CUDART_INF_F;
            int col = (s & 7) * 8 + 2 * l3;
            float e0 = (col < 29) ? acc0[0] : NI, e1 = (col + 1 < 29) ? acc0[1] : NI;
            float e2 = (col < 29) ? acc0[2] : NI, e3 = (col + 1 < 29) ? acc0[3] : NI;
            float e4 = (col < 29) ? acc1[0] : NI, e5 = (col + 1 < 29) ? acc1[1] : NI;
            float e6 = (col < 29) ? acc1[2] : NI, e7 = (col + 1 < 29) ? acc1[3] : NI;
            ins3p(h2(e0, e1), A0a, A0b, A0c);
            ins3p(h2(e2, e3), B0a, B0b, B0c);
            ins3p(h2(e4, e5), A1a, A1b, A1c);
            ins3p(h2(e6, e7), B1a, B1b, B1c);
        }
    };

    // unroll-2 ping-pong mainloop: no register copies (SPLS even)
    uint4 c0 = baseB[s0 * 64], c1 = baseB[s0 * 64 + 32];
#pragma unroll 1
    for (int s = s0; s < s1; s += 2) {
        const uint4* p1 = baseB + (s + 1) * 64;
        uint4 n0 = p1[0], n1 = p1[32];
        body(c0, c1, s);
        int s2 = (s + 2 < s1) ? s + 2 : s1 - 1;
        const uint4* p2 = baseB + s2 * 64;
        c0 = p2[0]; c1 = p2[32];
        body(n0, n1, s + 1);
    }

#pragma unroll
    for (int sh = 1; sh <= 2; sh <<= 1) {
        merge3p_shfl(sh, A0a, A0b, A0c);
        merge3p_shfl(sh, B0a, B0b, B0c);
        merge3p_shfl(sh, A1a, A1b, A1c);
        merge3p_shfl(sh, B1a, B1b, B1c);
    }

    if (w >= 4 && l3 == 0) {
        unsigned int* d = sRed + (rb * 8 + (lane >> 2)) * 12;
        d[0] = A0a; d[1] = A0b; d[2]  = A0c; d[3]  = B0a; d[4]  = B0b; d[5]  = B0c;
        d[6] = A1a; d[7] = A1b; d[8]  = A1c; d[9]  = B1a; d[10] = B1b; d[11] = B1c;
    }
    __syncthreads();
    if (w < 4 && l3 == 0) {
        const unsigned int* d = sRed + (rb * 8 + (lane >> 2)) * 12;
        ins3p(d[0], A0a, A0b, A0c); ins3p(d[1], A0a, A0b, A0c); ins3p(d[2], A0a, A0b, A0c);
        ins3p(d[3], B0a, B0b, B0c); ins3p(d[4], B0a, B0b, B0c); ins3p(d[5], B0a, B0b, B0c);
        ins3p(d[6], A1a, A1b, A1c); ins3p(d[7], A1a, A1b, A1c); ins3p(d[8], A1a, A1b, A1c);
        ins3p(d[9], B1a, B1b, B1c); ins3p(d[10], B1a, B1b, B1c); ins3p(d[11], B1a, B1b, B1c);

        const int entry = eBN * NQT + qt;
        const int row0 = rb * 32 + (lane >> 2);
        float4* outp = g_rowtri + ((long)entry * 128) * NSPL + ms;
        {
            float u0 = -CUDART_INF_F, u1 = u0, u2 = u0;
            unp_ins(A0a, u0, u1, u2); unp_ins(A0b, u0, u1, u2); unp_ins(A0c, u0, u1, u2);
            outp[(row0) * NSPL] = make_float4(u0, u1, u2, 0.f);
        }
        {
            float u0 = -CUDART_INF_F, u1 = u0, u2 = u0;
            unp_ins(B0a, u0, u1, u2); unp_ins(B0b, u0, u1, u2); unp_ins(B0c, u0, u1, u2);
            outp[(row0 + 8) * NSPL] = make_float4(u0, u1, u2, 0.f);
        }
        {
            float u0 = -CUDART_INF_F, u1 = u0, u2 = u0;
            unp_ins(A1a, u0, u1, u2); unp_ins(A1b, u0, u1, u2); unp_ins(A1c, u0, u1, u2);
            outp[(row0 + 16) * NSPL] = make_float4(u0, u1, u2, 0.f);
        }
        {
            float u0 = -CUDART_INF_F, u1 = u0, u2 = u0;
            unp_ins(B1a, u0, u1, u2); unp_ins(B1b, u0, u1, u2); unp_ins(B1c, u0, u1, u2);
            outp[(row0 + 24) * NSPL] = make_float4(u0, u1, u2, 0.f);
        }
    }

    // ---- fused finalize: last of the 8 CTAs for this (b,n) reduces & writes out ----
    __threadfence();
    __syncthreads();
    if (t == 0) {
        int old = atomicAdd(&g_cnt[eBN], 1);
        sLast = (old == 7) ? 1 : 0;
    }
    __syncthreads();
    if (!sLast) return;
    if (t == 0) g_cnt[eBN] = 0;     // self-reset for graph replay

    float val = 0.f;
#pragma unroll
    for (int i = 0; i < 2; i++) {
        int r = t + i * 256;        // padded rows hold {0,0,0} -> contribute 0
        int qti = r >> 7, row = r & 127;
        const float4* p = g_rowtri + ((long)((eBN * NQT + qti) * 128 + row)) * NSPL;
        float4 u = p[0], v = p[1];
        float t0 = u.x, t1 = u.y, t2 = u.z;
        ins3f(v.x, t0, t1, t2); ins3f(v.y, t0, t1, t2); ins3f(v.z, t0, t1, t2);
        val += t0 + t1 + t2;
    }
#pragma unroll
    for (int sh = 16; sh > 0; sh >>= 1) val += __shfl_xor_sync(0xffffffffu, val, sh);
    if (lane == 0) sVal[w] = val;
    __syncthreads();
    if (t == 0) {
        float x = 0.f;
#pragma unroll
        for (int i = 0; i < 8; i++) x += sVal[i];
        out[eBN] = x;
    }
}

extern "C" void kernel_launch(void* const* d_in, const int* in_sizes, int n_in,
                              void* d_out, int out_size) {
    const float* x1 = (const float*)d_in[0];
    const float* x2 = (const float*)d_in[1];
    float* out = (float*)d_out;

    norm_kernel<<<(NROW * 32 + 255) / 256, 256>>>(x1, x2);
    frag_kernel<<<(NA4 + NB4 + 255) / 256, 256>>>(x2);
    noop_kernel<<<1, 32>>>();   // places fused kernel at captured launch idx 5
    fused_metric_kernel<<<dim3(NQT * NSPL, NCLS, BDIM), 256>>>(out);
}